// round 5
// baseline (speedup 1.0000x reference)
#include <cuda_runtime.h>
#include <cstdint>
#include <cstddef>

#define B 8
#define L 2048
#define E 128
#define KC 64

// ---------------- scratch (device globals) ----------------------------------
__device__ float g_S[(size_t)B * L * L];      // exp(S*mask), tf32-rounded
__device__ float g_TT[(size_t)B * E * L];     // TT[e][j] = invd[j]^2 * sum_i Uid[i,e] expS[i,j]
__device__ float g_UqsT[(size_t)B * E * L];   // UqsT[e][j] = invd[j] * Uq[j,e]  (tf32)
__device__ float g_UidT[(size_t)B * E * L];   // UidT[e][i] = Uid[i,e]           (tf32)
__device__ float g_Uidw[(size_t)B * L * E];   // tf32(Uid * wmul)
__device__ float g_Uqr [(size_t)B * L * E];   // tf32(Uq)
__device__ float g_sid[B * L];
__device__ float g_sq[B * L];
__device__ float g_d[B * L];
__device__ float g_invd[B * L];

// ---------------- helpers ----------------------------------------------------
__device__ __forceinline__ float tf32r(float x) {
    uint32_t u;
    asm("cvt.rna.tf32.f32 %0, %1;" : "=r"(u) : "f"(x));
    return __uint_as_float(u);
}
__device__ __forceinline__ uint32_t smem_u32(const void* p) {
    uint32_t a;
    asm("{ .reg .u64 t; cvta.to.shared.u64 t, %1; cvt.u32.u64 %0, t; }"
        : "=r"(a) : "l"(p));
    return a;
}
__device__ __forceinline__ void ldsm4(uint32_t addr, uint32_t r[4]) {
    asm volatile("ldmatrix.sync.aligned.m8n8.x4.shared.b16 {%0,%1,%2,%3}, [%4];"
                 : "=r"(r[0]), "=r"(r[1]), "=r"(r[2]), "=r"(r[3]) : "r"(addr));
}
__device__ __forceinline__ void mma1688(float c[4], const uint32_t a[4],
                                        uint32_t b0, uint32_t b1) {
    asm volatile(
        "mma.sync.aligned.m16n8k8.row.col.f32.tf32.tf32.f32 "
        "{%0,%1,%2,%3}, {%4,%5,%6,%7}, {%8,%9}, {%0,%1,%2,%3};"
        : "+f"(c[0]), "+f"(c[1]), "+f"(c[2]), "+f"(c[3])
        : "r"(a[0]), "r"(a[1]), "r"(a[2]), "r"(a[3]), "r"(b0), "r"(b1));
}

// ---------------- cp.async ---------------------------------------------------
__device__ __forceinline__ void cpa16(uint32_t dst, const float* src) {
    asm volatile("cp.async.cg.shared.global [%0], [%1], 16;"
                 :: "r"(dst), "l"(src) : "memory");
}
__device__ __forceinline__ void cpa_commit() {
    asm volatile("cp.async.commit_group;" ::: "memory");
}
__device__ __forceinline__ void cpa_wait1() {
    asm volatile("cp.async.wait_group 1;" ::: "memory");
}
__device__ __forceinline__ void cpa_wait0() {
    asm volatile("cp.async.wait_group 0;" ::: "memory");
}

// ---------------- kernel 1: row dots s_id, s_q + zero g_d -------------------
__global__ void k_dots(const float* __restrict__ Uq,
                       const float* __restrict__ Uid,
                       const float* __restrict__ Wc_w) {
    int r = blockIdx.x * 8 + threadIdx.y;
    int lane = threadIdx.x;
    float sid = 0.f, sq = 0.f;
#pragma unroll
    for (int t = 0; t < 4; t++) {
        int e = lane + t * 32;
        sid += Uid[(size_t)r * E + e] * Wc_w[e];
        sq  += Uq [(size_t)r * E + e] * Wc_w[E + e];
    }
#pragma unroll
    for (int o = 16; o; o >>= 1) {
        sid += __shfl_xor_sync(0xffffffffu, sid, o);
        sq  += __shfl_xor_sync(0xffffffffu, sq,  o);
    }
    if (lane == 0) { g_sid[r] = sid; g_sq[r] = sq; g_d[r] = 0.f; }
}

// ---------------- kernel 1b: pre-rounded operands ---------------------------
__global__ void k_prep(const float* __restrict__ Uq,
                       const float* __restrict__ Uid,
                       const float* __restrict__ Wc_w) {
    size_t idx = ((size_t)blockIdx.x * 256 + threadIdx.x) * 4;
    int c = (int)(idx & (E - 1));
    float4 u = *(const float4*)&Uid[idx];
    float4 q = *(const float4*)&Uq[idx];
    float4 w = *(const float4*)&Wc_w[2 * E + c];
    float4 o1, o2;
    o1.x = tf32r(u.x * w.x); o1.y = tf32r(u.y * w.y);
    o1.z = tf32r(u.z * w.z); o1.w = tf32r(u.w * w.w);
    o2.x = tf32r(q.x); o2.y = tf32r(q.y); o2.z = tf32r(q.z); o2.w = tf32r(q.w);
    *(float4*)&g_Uidw[idx] = o1;
    *(float4*)&g_Uqr[idx]  = o2;
}

// ---------------- kernel 2: expS + column sums, batch-looped ----------------
// One CTA owns one (i,j) 128x128 tile and loops over all 8 batches; the mask
// fragment lives in registers.  Double-buffered cp.async over (batch, k-chunk).
#define SGP 68
__global__ __launch_bounds__(256, 1) void k_sgemm(const float* __restrict__ mask,
                                                  const float* __restrict__ Wc_b) {
    extern __shared__ float sm[];
    float* As = sm;                       // [2][128][SGP]
    float* Bs = sm + 2 * 128 * SGP;       // [2][128][SGP]
    float* red = Bs + 2 * 128 * SGP;      // [128]
    const int stS = 128 * SGP;
    int i0 = blockIdx.y * 128;
    int j0 = blockIdx.x * 128;
    int tid = threadIdx.x, lane = tid & 31, wid = tid >> 5;
    int wm = wid & 3, wn = wid >> 2;      // 4m x 2n warps, warp tile 32x64

    uint32_t aBase = smem_u32(As), bBase = smem_u32(Bs);
    float bias = *Wc_b;

    // mask fragment: 64 values per thread, shared by all batches
    float mfrag[2][8][4];
#pragma unroll
    for (int mi = 0; mi < 2; mi++) {
        int r0 = i0 + wm * 32 + mi * 16 + (lane >> 2);
#pragma unroll
        for (int nt = 0; nt < 8; nt++) {
            int n = j0 + wn * 64 + nt * 8 + (lane & 3) * 2;
            float2 mk0 = *(const float2*)&mask[(size_t)r0 * L + n];
            float2 mk1 = *(const float2*)&mask[(size_t)(r0 + 8) * L + n];
            mfrag[mi][nt][0] = mk0.x; mfrag[mi][nt][1] = mk0.y;
            mfrag[mi][nt][2] = mk1.x; mfrag[mi][nt][3] = mk1.y;
        }
    }

    auto load = [&](int it) {            // it = b*2 + chunk
        int b = it >> 1, k0 = (it & 1) * KC, s = it & 1;
        const float* A = g_Uidw + (size_t)b * L * E;
        const float* Bq = g_Uqr + (size_t)b * L * E;
#pragma unroll
        for (int p = 0; p < 8; p++) {
            int idx = tid + p * 256;
            int row = idx >> 4, q = (idx & 15) * 4;
            cpa16(aBase + (s * stS + row * SGP + q) * 4,
                  &A[(size_t)(i0 + row) * E + k0 + q]);
        }
#pragma unroll
        for (int p = 0; p < 8; p++) {
            int idx = tid + p * 256;
            int row = idx >> 4, q = (idx & 15) * 4;
            cpa16(bBase + (s * stS + row * SGP + q) * 4,
                  &Bq[(size_t)(j0 + row) * E + k0 + q]);
        }
        cpa_commit();
    };

    float acc[2][8][4];
#pragma unroll
    for (int mi = 0; mi < 2; mi++)
#pragma unroll
        for (int nt = 0; nt < 8; nt++)
#pragma unroll
            for (int q = 0; q < 4; q++) acc[mi][nt][q] = 0.f;

    int fr = (lane & 15) * SGP + (lane >> 4) * 4;
    const int ITERS = 2 * B;
    load(0); load(1);
    for (int it = 0; it < ITERS; it++) {
        int s = it & 1;
        if (it + 1 < ITERS) cpa_wait1(); else cpa_wait0();
        __syncthreads();
#pragma unroll
        for (int kk = 0; kk < 8; kk++) {
            uint32_t a[2][4], bf[4][4];
#pragma unroll
            for (int mi = 0; mi < 2; mi++)
                ldsm4(aBase + (s * stS + (wm * 32 + mi * 16) * SGP + kk * 8 + fr) * 4, a[mi]);
#pragma unroll
            for (int n4 = 0; n4 < 4; n4++)
                ldsm4(bBase + (s * stS + (wn * 64 + n4 * 16) * SGP + kk * 8 + fr) * 4, bf[n4]);
#pragma unroll
            for (int n4 = 0; n4 < 4; n4++)
#pragma unroll
                for (int h = 0; h < 2; h++)
#pragma unroll
                    for (int mi = 0; mi < 2; mi++)
                        mma1688(acc[mi][n4 * 2 + h], a[mi], bf[n4][h], bf[n4][h + 2]);
        }
        if (tid < 128 && (it & 1)) red[tid] = 0.f;
        __syncthreads();
        if (it + 2 < ITERS) load(it + 2);
        if (it & 1) {
            // epilogue for batch b = it >> 1
            int b = it >> 1;
            float* Sout = g_S + (size_t)b * L * L;
            float cs0[8], cs1[8];
#pragma unroll
            for (int nt = 0; nt < 8; nt++) { cs0[nt] = 0.f; cs1[nt] = 0.f; }
#pragma unroll
            for (int mi = 0; mi < 2; mi++) {
                int r0 = i0 + wm * 32 + mi * 16 + (lane >> 2);
                float sidv0 = g_sid[b * L + r0];
                float sidv1 = g_sid[b * L + r0 + 8];
#pragma unroll
                for (int nt = 0; nt < 8; nt++) {
                    int n = j0 + wn * 64 + nt * 8 + (lane & 3) * 2;
                    float2 sq2 = *(const float2*)&g_sq[b * L + n];
                    float e0 = tf32r(__expf((acc[mi][nt][0] + sidv0 + sq2.x + bias) * mfrag[mi][nt][0]));
                    float e1 = tf32r(__expf((acc[mi][nt][1] + sidv0 + sq2.y + bias) * mfrag[mi][nt][1]));
                    float e2 = tf32r(__expf((acc[mi][nt][2] + sidv1 + sq2.x + bias) * mfrag[mi][nt][2]));
                    float e3 = tf32r(__expf((acc[mi][nt][3] + sidv1 + sq2.y + bias) * mfrag[mi][nt][3]));
                    *(float2*)&Sout[(size_t)r0 * L + n]       = make_float2(e0, e1);
                    *(float2*)&Sout[(size_t)(r0 + 8) * L + n] = make_float2(e2, e3);
                    cs0[nt] += e0 + e2;
                    cs1[nt] += e1 + e3;
                    acc[mi][nt][0] = 0.f; acc[mi][nt][1] = 0.f;
                    acc[mi][nt][2] = 0.f; acc[mi][nt][3] = 0.f;
                }
            }
#pragma unroll
            for (int o = 16; o >= 4; o >>= 1)
#pragma unroll
                for (int nt = 0; nt < 8; nt++) {
                    cs0[nt] += __shfl_xor_sync(0xffffffffu, cs0[nt], o);
                    cs1[nt] += __shfl_xor_sync(0xffffffffu, cs1[nt], o);
                }
            if ((lane >> 2) == 0) {
#pragma unroll
                for (int nt = 0; nt < 8; nt++) {
                    int nl = wn * 64 + nt * 8 + (lane & 3) * 2;
                    atomicAdd(&red[nl], cs0[nt]);
                    atomicAdd(&red[nl + 1], cs1[nt]);
                }
            }
            __syncthreads();
            if (tid < 128) atomicAdd(&g_d[(size_t)b * L + j0 + tid], red[tid]);
        }
    }
}

// ---------------- kernel 3: invd = 1/d --------------------------------------
__global__ void k_inv() {
    int r = blockIdx.x * 256 + threadIdx.x;
    g_invd[r] = 1.0f / g_d[r];
}

// ---------------- kernel 4: transposes -> tf32  Uid->UidT, invd*Uq->UqsT ----
__global__ void k_trans(const float* __restrict__ Uid,
                        const float* __restrict__ Uq) {
    __shared__ float t[32][33];
    int l0 = blockIdx.x * 32, e0 = blockIdx.y * 32;
    int b = blockIdx.z >> 1, mat = blockIdx.z & 1;
    const float* src = (mat ? Uq : Uid) + (size_t)b * L * E;
    int tx = threadIdx.x, ty = threadIdx.y;
#pragma unroll
    for (int r = 0; r < 4; r++)
        t[ty + r * 8][tx] = src[(size_t)(l0 + ty + r * 8) * E + e0 + tx];
    __syncthreads();
    float inv = mat ? g_invd[b * L + l0 + tx] : 1.0f;
    float* dst = (mat ? g_UqsT : g_UidT) + (size_t)b * E * L;
#pragma unroll
    for (int r = 0; r < 4; r++)
        dst[(size_t)(e0 + ty + r * 8) * L + l0 + tx] = tf32r(t[tx][ty + r * 8] * inv);
}

// ---------------- kernel 5: TT = invd^2 * (UidT @ expS)   tf32 mma ----------
#define TAP 68
#define TBP 136
__global__ __launch_bounds__(256, 1) void k_tgemm2() {
    extern __shared__ float sm[];
    float* As = sm;                       // [2][128][TAP]
    float* Bs = sm + 2 * 128 * TAP;       // [2][KC][TBP]
    const int stA = 128 * TAP, stB = KC * TBP;
    int tid = threadIdx.x, lane = tid & 31, wid = tid >> 5;
    int wm = wid & 3, wn = wid >> 2;      // 4 x 2, warp tile 32m x 64n
    int b = blockIdx.y;
    int j0 = blockIdx.x * 128;
    const float* Ab = g_UidT + (size_t)b * E * L;
    const float* Sb = g_S + (size_t)b * L * L;

    uint32_t aBase = smem_u32(As), bBase = smem_u32(Bs);

    auto load = [&](int t) {
        int k0 = t * KC, s = t & 1;
#pragma unroll
        for (int p = 0; p < 8; p++) {
            int idx = tid + p * 256;
            int row = idx >> 4, q = (idx & 15) * 4;
            cpa16(aBase + (s * stA + row * TAP + q) * 4, &Ab[(size_t)row * L + k0 + q]);
        }
#pragma unroll
        for (int p = 0; p < 8; p++) {
            int idx = tid + p * 256;
            int i = idx >> 5, j4 = (idx & 31) * 4;
            cpa16(bBase + (s * stB + i * TBP + j4) * 4,
                  &Sb[(size_t)(k0 + i) * L + j0 + j4]);
        }
        cpa_commit();
    };

    float acc[2][8][4];
#pragma unroll
    for (int mi = 0; mi < 2; mi++)
#pragma unroll
        for (int nt = 0; nt < 8; nt++)
#pragma unroll
            for (int q = 0; q < 4; q++) acc[mi][nt][q] = 0.f;

    int frA = (lane & 15) * TAP + (lane >> 4) * 4;
    const int iters = L / KC;
    load(0); load(1);
    for (int t = 0; t < iters; t++) {
        int s = t & 1;
        if (t + 1 < iters) cpa_wait1(); else cpa_wait0();
        __syncthreads();
        const float* Bss = Bs + s * stB;
#pragma unroll
        for (int kk = 0; kk < 8; kk++) {
            uint32_t a[2][4];
#pragma unroll
            for (int mi = 0; mi < 2; mi++)
                ldsm4(aBase + (s * stA + (wm * 32 + mi * 16) * TAP + kk * 8 + frA) * 4, a[mi]);
#pragma unroll
            for (int nt = 0; nt < 8; nt++) {
                const float* bp = &Bss[(kk * 8 + (lane & 3)) * TBP +
                                       wn * 64 + nt * 8 + (lane >> 2)];
                uint32_t b0 = __float_as_uint(bp[0]);
                uint32_t b1 = __float_as_uint(bp[4 * TBP]);
#pragma unroll
                for (int mi = 0; mi < 2; mi++) mma1688(acc[mi][nt], a[mi], b0, b1);
            }
        }
        __syncthreads();
        if (t + 2 < iters) load(t + 2);
    }

#pragma unroll
    for (int mi = 0; mi < 2; mi++) {
        int e0r = wm * 32 + mi * 16 + (lane >> 2);
#pragma unroll
        for (int nt = 0; nt < 8; nt++) {
            int j = j0 + wn * 64 + nt * 8 + (lane & 3) * 2;
            float2 iv = *(const float2*)&g_invd[b * L + j];
            float s0 = iv.x * iv.x, s1 = iv.y * iv.y;
            float* d0 = &g_TT[((size_t)b * E + e0r) * L + j];
            float* d1 = &g_TT[((size_t)b * E + e0r + 8) * L + j];
            *(float2*)d0 = make_float2(tf32r(acc[mi][nt][0] * s0), tf32r(acc[mi][nt][1] * s1));
            *(float2*)d1 = make_float2(tf32r(acc[mi][nt][2] * s0), tf32r(acc[mi][nt][3] * s1));
        }
    }
}

// ---------------- kernel 6: [A_D2Q | A_Q2D] = expS @ [UqsT | TT]^T ----------
// CTA 128m x 256n, 512 threads (4m x 4n warps, warp tile 32x64).
__global__ __launch_bounds__(512, 1) void k_final(const float* __restrict__ Uid,
                                                  float* __restrict__ out) {
    extern __shared__ float sm[];
    float* As = sm;                       // [2][128][TAP]
    float* Bs = sm + 2 * 128 * TAP;       // [2][256][TAP]
    const int stA = 128 * TAP, stB = 256 * TAP;
    int tid = threadIdx.x, lane = tid & 31, wid = tid >> 5;
    int wm = wid & 3, wn = wid >> 2;      // 4 x 4
    int b = blockIdx.y;
    int i0 = blockIdx.x * 128;
    const float* Sb  = g_S    + (size_t)b * L * L + (size_t)i0 * L;
    const float* B1g = g_UqsT + (size_t)b * E * L;
    const float* B2g = g_TT   + (size_t)b * E * L;

    uint32_t aBase = smem_u32(As), bBase = smem_u32(Bs);

    auto load = [&](int t) {
        int k0 = t * KC, s = t & 1;
#pragma unroll
        for (int p = 0; p < 4; p++) {
            int idx = tid + p * 512;
            int row = idx >> 4, q = (idx & 15) * 4;
            cpa16(aBase + (s * stA + row * TAP + q) * 4, &Sb[(size_t)row * L + k0 + q]);
        }
#pragma unroll
        for (int p = 0; p < 8; p++) {
            int idx = tid + p * 512;
            int row = idx >> 4, q = (idx & 15) * 4;
            const float* src = row < 128 ? &B1g[(size_t)row * L + k0 + q]
                                         : &B2g[(size_t)(row - 128) * L + k0 + q];
            cpa16(bBase + (s * stB + row * TAP + q) * 4, src);
        }
        cpa_commit();
    };

    float acc[2][8][4];
#pragma unroll
    for (int mi = 0; mi < 2; mi++)
#pragma unroll
        for (int nt = 0; nt < 8; nt++)
#pragma unroll
            for (int q = 0; q < 4; q++) acc[mi][nt][q] = 0.f;

    int fr = (lane & 15) * TAP + (lane >> 4) * 4;
    const int iters = L / KC;
    load(0); load(1);
    for (int t = 0; t < iters; t++) {
        int s = t & 1;
        if (t + 1 < iters) cpa_wait1(); else cpa_wait0();
        __syncthreads();
#pragma unroll
        for (int kk = 0; kk < 8; kk++) {
            uint32_t a[2][4], bf[4][4];
#pragma unroll
            for (int mi = 0; mi < 2; mi++)
                ldsm4(aBase + (s * stA + (wm * 32 + mi * 16) * TAP + kk * 8 + fr) * 4, a[mi]);
#pragma unroll
            for (int n4 = 0; n4 < 4; n4++)
                ldsm4(bBase + (s * stB + (wn * 64 + n4 * 16) * TAP + kk * 8 + fr) * 4, bf[n4]);
#pragma unroll
            for (int n4 = 0; n4 < 4; n4++)
#pragma unroll
                for (int h = 0; h < 2; h++)
#pragma unroll
                    for (int mi = 0; mi < 2; mi++)
                        mma1688(acc[mi][n4 * 2 + h], a[mi], bf[n4][h], bf[n4][h + 2]);
        }
        __syncthreads();
        if (t + 2 < iters) load(t + 2);
    }

    // epilogue: out row i: [Uid | A_D2Q | Uid*A_D2Q | Uid*A_Q2D]
#pragma unroll
    for (int mi = 0; mi < 2; mi++) {
        int r0 = i0 + wm * 32 + mi * 16 + (lane >> 2);
#pragma unroll
        for (int nt = 0; nt < 8; nt++) {
            int n = wn * 64 + nt * 8 + (lane & 3) * 2;   // 0..255
#pragma unroll
            for (int h = 0; h < 2; h++) {
                int gi = r0 + h * 8;
                float v0 = acc[mi][nt][h * 2], v1 = acc[mi][nt][h * 2 + 1];
                float* orow = out + ((size_t)b * L + gi) * (4 * E);
                if (n < 128) {
                    float2 u = *(const float2*)&Uid[((size_t)b * L + gi) * E + n];
                    *(float2*)&orow[128 + n] = make_float2(v0, v1);
                    *(float2*)&orow[256 + n] = make_float2(v0 * u.x, v1 * u.y);
                } else {
                    int m = n - 128;
                    float2 u = *(const float2*)&Uid[((size_t)b * L + gi) * E + m];
                    *(float2*)&orow[384 + m] = make_float2(v0 * u.x, v1 * u.y);
                }
            }
        }
    }
    // Uid copy into slot 0
#pragma unroll
    for (int p = 0; p < 8; p++) {
        int idx = tid + p * 512;
        int row = idx >> 5, c = (idx & 31) * 4;
        int gi = i0 + row;
        *(float4*)&out[((size_t)b * L + gi) * (4 * E) + c] =
            *(const float4*)&Uid[((size_t)b * L + gi) * E + c];
    }
}

// ---------------- launch ----------------------------------------------------
extern "C" void kernel_launch(void* const* d_in, const int* in_sizes, int n_in,
                              void* d_out, int out_size) {
    const float* Uq   = (const float*)d_in[0];
    const float* Uid  = (const float*)d_in[1];
    const float* mask = (const float*)d_in[2];
    const float* Wc_w = (const float*)d_in[3];
    const float* Wc_b = (const float*)d_in[4];
    float* out = (float*)d_out;

    const int SMEM_SG = (2 * 128 * SGP * 2 + 128) * 4;             // 139776
    const int SMEM_TG = (2 * 128 * TAP + 2 * KC * TBP) * 4;        // 139264
    const int SMEM_FI = (2 * 128 * TAP + 2 * 256 * TAP) * 4;       // 208896
    cudaFuncSetAttribute(k_sgemm,  cudaFuncAttributeMaxDynamicSharedMemorySize, SMEM_SG);
    cudaFuncSetAttribute(k_tgemm2, cudaFuncAttributeMaxDynamicSharedMemorySize, SMEM_TG);
    cudaFuncSetAttribute(k_final,  cudaFuncAttributeMaxDynamicSharedMemorySize, SMEM_FI);

    k_dots<<<(B * L) / 8, dim3(32, 8)>>>(Uq, Uid, Wc_w);
    k_prep<<<(B * L * E) / 1024, 256>>>(Uq, Uid, Wc_w);
    k_sgemm<<<dim3(L / 128, L / 128), 256, SMEM_SG>>>(mask, Wc_b);
    k_inv<<<(B * L) / 256, 256>>>();
    k_trans<<<dim3(L / 32, E / 32, 2 * B), dim3(32, 8)>>>(Uid, Uq);
    k_tgemm2<<<dim3(L / 128, B), 256, SMEM_TG>>>();
    k_final<<<dim3(L / 128, B), 512, SMEM_FI>>>(Uid, out);
}

// round 6
// speedup vs baseline: 1.7663x; 1.7663x over previous
#include <cuda_runtime.h>
#include <cuda_fp16.h>
#include <cstdint>
#include <cstddef>

#define B 8
#define L 2048
#define E 128
#define HP 136                     // smem pitch in halves (272B, ldmatrix conflict-free)

// ---------------- scratch (device globals) ----------------------------------
__device__ half g_Sh[(size_t)B * L * L];      // fp16(exp(S*mask))            67 MB
__device__ half g_Th[(size_t)B * E * L];      // fp16(invd^2 * G2 * 2^14)   [e][j]
__device__ half g_Uqsh[(size_t)B * E * L];    // fp16(invd * Uq^T * 2^10)   [e][j]
__device__ half g_UidTh[(size_t)B * E * L];   // fp16(Uid^T)                [e][i]
__device__ half g_Uidwh[(size_t)B * L * E];   // fp16(Uid * wmul)           [i][e]
__device__ half g_Uqh[(size_t)B * L * E];     // fp16(Uq)                   [j][e]
__device__ float g_sid[B * L];
__device__ float g_sq[B * L];
__device__ float g_d[B * L];
__device__ float g_invd[B * L];

#define SC_QI 0.0009765625f        // 2^-10
#define SC_TI 6.103515625e-05f     // 2^-14

// ---------------- helpers ----------------------------------------------------
__device__ __forceinline__ uint32_t smem_u32(const void* p) {
    uint32_t a;
    asm("{ .reg .u64 t; cvta.to.shared.u64 t, %1; cvt.u32.u64 %0, t; }"
        : "=r"(a) : "l"(p));
    return a;
}
__device__ __forceinline__ void ldsm4(uint32_t addr, uint32_t r[4]) {
    asm volatile("ldmatrix.sync.aligned.m8n8.x4.shared.b16 {%0,%1,%2,%3}, [%4];"
                 : "=r"(r[0]), "=r"(r[1]), "=r"(r[2]), "=r"(r[3]) : "r"(addr));
}
__device__ __forceinline__ void ldsm4t(uint32_t addr, uint32_t r[4]) {
    asm volatile("ldmatrix.sync.aligned.m8n8.x4.trans.shared.b16 {%0,%1,%2,%3}, [%4];"
                 : "=r"(r[0]), "=r"(r[1]), "=r"(r[2]), "=r"(r[3]) : "r"(addr));
}
__device__ __forceinline__ void mma16816(float c[4], const uint32_t a[4],
                                         uint32_t b0, uint32_t b1) {
    asm volatile(
        "mma.sync.aligned.m16n8k16.row.col.f32.f16.f16.f32 "
        "{%0,%1,%2,%3}, {%4,%5,%6,%7}, {%8,%9}, {%0,%1,%2,%3};"
        : "+f"(c[0]), "+f"(c[1]), "+f"(c[2]), "+f"(c[3])
        : "r"(a[0]), "r"(a[1]), "r"(a[2]), "r"(a[3]), "r"(b0), "r"(b1));
}
__device__ __forceinline__ void cpa16(uint32_t dst, const void* src) {
    asm volatile("cp.async.cg.shared.global [%0], [%1], 16;"
                 :: "r"(dst), "l"(src) : "memory");
}
__device__ __forceinline__ void cpa_commit() {
    asm volatile("cp.async.commit_group;" ::: "memory");
}
__device__ __forceinline__ void cpa_wait1() {
    asm volatile("cp.async.wait_group 1;" ::: "memory");
}
__device__ __forceinline__ void cpa_wait0() {
    asm volatile("cp.async.wait_group 0;" ::: "memory");
}

// ---------------- kernel 1: row dots s_id, s_q + zero g_d -------------------
__global__ void k_dots(const float* __restrict__ Uq,
                       const float* __restrict__ Uid,
                       const float* __restrict__ Wc_w) {
    int r = blockIdx.x * 8 + threadIdx.y;
    int lane = threadIdx.x;
    float sid = 0.f, sq = 0.f;
#pragma unroll
    for (int t = 0; t < 4; t++) {
        int e = lane + t * 32;
        sid += Uid[(size_t)r * E + e] * Wc_w[e];
        sq  += Uq [(size_t)r * E + e] * Wc_w[E + e];
    }
#pragma unroll
    for (int o = 16; o; o >>= 1) {
        sid += __shfl_xor_sync(0xffffffffu, sid, o);
        sq  += __shfl_xor_sync(0xffffffffu, sq,  o);
    }
    if (lane == 0) { g_sid[r] = sid; g_sq[r] = sq; g_d[r] = 0.f; }
}

// ---------------- kernel 1b: fp16 operands for GEMM1 ------------------------
__global__ void k_prep(const float* __restrict__ Uq,
                       const float* __restrict__ Uid,
                       const float* __restrict__ Wc_w) {
    size_t i4 = ((size_t)blockIdx.x * 256 + threadIdx.x) * 4;
    int c = (int)(i4 & (E - 1));
    float4 u = *(const float4*)&Uid[i4];
    float4 q = *(const float4*)&Uq[i4];
    float4 w = *(const float4*)&Wc_w[2 * E + c];
    half2 a0 = __floats2half2_rn(u.x * w.x, u.y * w.y);
    half2 a1 = __floats2half2_rn(u.z * w.z, u.w * w.w);
    half2 q0 = __floats2half2_rn(q.x, q.y);
    half2 q1 = __floats2half2_rn(q.z, q.w);
    *(half2*)&g_Uidwh[i4]     = a0;
    *(half2*)&g_Uidwh[i4 + 2] = a1;
    *(half2*)&g_Uqh[i4]       = q0;
    *(half2*)&g_Uqh[i4 + 2]   = q1;
}

// ---------------- kernel 2: Sh = fp16(exp(S*mask)) + column sums ------------
// per-(b,i0,j0) CTA; fp16 mma K=128 single-shot.
__global__ __launch_bounds__(256) void k_sgemm(const float* __restrict__ mask,
                                               const float* __restrict__ Wc_b) {
    extern __shared__ char smc[];
    half* Ah = (half*)smc;                       // [128][HP]
    half* Bh = Ah + 128 * HP;                    // [128][HP]
    float* red = (float*)(Bh + 128 * HP);        // [128]
    int b  = blockIdx.z;
    int i0 = blockIdx.y * 128;
    int j0 = blockIdx.x * 128;
    int tid = threadIdx.x, lane = tid & 31, wid = tid >> 5;
    int wm = wid & 3, wn = wid >> 2;             // 4m x 2n warps, tile 32x64
    const half* A  = g_Uidwh + (size_t)b * L * E;
    const half* Bq = g_Uqh   + (size_t)b * L * E;
    uint32_t aB = smem_u32(Ah), bB = smem_u32(Bh);

#pragma unroll
    for (int p = 0; p < 8; p++) {
        int idx = tid + p * 256;
        int row = idx >> 4, q = (idx & 15) * 8;
        cpa16(aB + (row * HP + q) * 2, A + (size_t)(i0 + row) * E + q);
    }
#pragma unroll
    for (int p = 0; p < 8; p++) {
        int idx = tid + p * 256;
        int row = idx >> 4, q = (idx & 15) * 8;
        cpa16(bB + (row * HP + q) * 2, Bq + (size_t)(j0 + row) * E + q);
    }
    cpa_commit();
    if (tid < 128) red[tid] = 0.f;
    cpa_wait0();
    __syncthreads();

    float acc[2][8][4];
#pragma unroll
    for (int mi = 0; mi < 2; mi++)
#pragma unroll
        for (int nt = 0; nt < 8; nt++)
#pragma unroll
            for (int q = 0; q < 4; q++) acc[mi][nt][q] = 0.f;

#pragma unroll
    for (int kk = 0; kk < 8; kk++) {
        uint32_t a[2][4], bf[4][4];
#pragma unroll
        for (int mi = 0; mi < 2; mi++)
            ldsm4(aB + ((wm * 32 + mi * 16 + (lane & 15)) * HP + kk * 16 + (lane >> 4) * 8) * 2, a[mi]);
#pragma unroll
        for (int n4 = 0; n4 < 4; n4++)
            ldsm4(bB + ((wn * 64 + n4 * 16 + (lane & 15)) * HP + kk * 16 + (lane >> 4) * 8) * 2, bf[n4]);
#pragma unroll
        for (int n4 = 0; n4 < 4; n4++)
#pragma unroll
            for (int mi = 0; mi < 2; mi++) {
                mma16816(acc[mi][n4 * 2 + 0], a[mi], bf[n4][0], bf[n4][2]);
                mma16816(acc[mi][n4 * 2 + 1], a[mi], bf[n4][1], bf[n4][3]);
            }
    }

    float bias = *Wc_b;
    half* Sout = g_Sh + (size_t)b * L * L;
    float cs0[8], cs1[8];
#pragma unroll
    for (int nt = 0; nt < 8; nt++) { cs0[nt] = 0.f; cs1[nt] = 0.f; }
#pragma unroll
    for (int mi = 0; mi < 2; mi++) {
        int r0 = i0 + wm * 32 + mi * 16 + (lane >> 2);
        float sidv0 = g_sid[b * L + r0];
        float sidv1 = g_sid[b * L + r0 + 8];
#pragma unroll
        for (int nt = 0; nt < 8; nt++) {
            int n = j0 + wn * 64 + nt * 8 + (lane & 3) * 2;
            float2 sq2 = *(const float2*)&g_sq[b * L + n];
            float2 mk0 = *(const float2*)&mask[(size_t)r0 * L + n];
            float2 mk1 = *(const float2*)&mask[(size_t)(r0 + 8) * L + n];
            float e0 = __expf((acc[mi][nt][0] + sidv0 + sq2.x + bias) * mk0.x);
            float e1 = __expf((acc[mi][nt][1] + sidv0 + sq2.y + bias) * mk0.y);
            float e2 = __expf((acc[mi][nt][2] + sidv1 + sq2.x + bias) * mk1.x);
            float e3 = __expf((acc[mi][nt][3] + sidv1 + sq2.y + bias) * mk1.y);
            half2 h01 = __floats2half2_rn(e0, e1);
            half2 h23 = __floats2half2_rn(e2, e3);
            *(half2*)&Sout[(size_t)r0 * L + n]       = h01;
            *(half2*)&Sout[(size_t)(r0 + 8) * L + n] = h23;
            float r0v = __low2float(h01), r1v = __high2float(h01);
            float r2v = __low2float(h23), r3v = __high2float(h23);
            cs0[nt] += r0v + r2v;
            cs1[nt] += r1v + r3v;
        }
    }
#pragma unroll
    for (int o = 16; o >= 4; o >>= 1)
#pragma unroll
        for (int nt = 0; nt < 8; nt++) {
            cs0[nt] += __shfl_xor_sync(0xffffffffu, cs0[nt], o);
            cs1[nt] += __shfl_xor_sync(0xffffffffu, cs1[nt], o);
        }
    if ((lane >> 2) == 0) {
#pragma unroll
        for (int nt = 0; nt < 8; nt++) {
            int nl = wn * 64 + nt * 8 + (lane & 3) * 2;
            atomicAdd(&red[nl], cs0[nt]);
            atomicAdd(&red[nl + 1], cs1[nt]);
        }
    }
    __syncthreads();
    if (tid < 128) atomicAdd(&g_d[(size_t)b * L + j0 + tid], red[tid]);
}

// ---------------- kernel 3: invd = 1/d --------------------------------------
__global__ void k_inv() {
    int r = blockIdx.x * 256 + threadIdx.x;
    g_invd[r] = 1.0f / g_d[r];
}

// ---------------- kernel 4: transposes -> fp16 ------------------------------
// mat 0: UidTh[e][i] = Uid[i,e];  mat 1: Uqsh[e][j] = invd[j]*Uq[j,e]*2^10
__global__ void k_trans(const float* __restrict__ Uid,
                        const float* __restrict__ Uq) {
    __shared__ float t[32][33];
    int l0 = blockIdx.x * 32, e0 = blockIdx.y * 32;
    int b = blockIdx.z >> 1, mat = blockIdx.z & 1;
    const float* src = (mat ? Uq : Uid) + (size_t)b * L * E;
    int tx = threadIdx.x, ty = threadIdx.y;
#pragma unroll
    for (int r = 0; r < 4; r++)
        t[ty + r * 8][tx] = src[(size_t)(l0 + ty + r * 8) * E + e0 + tx];
    __syncthreads();
    float inv = mat ? g_invd[b * L + l0 + tx] * 1024.0f : 1.0f;
    half* dst = (mat ? g_Uqsh : g_UidTh) + (size_t)b * E * L;
#pragma unroll
    for (int r = 0; r < 4; r++)
        dst[(size_t)(e0 + ty + r * 8) * L + l0 + tx] =
            __float2half_rn(t[tx][ty + r * 8] * inv);
}

// ---------------- kernel 5: Th = fp16(invd^2 * (UidTh @ Sh) * 2^14) ---------
// C[e][j] over K=i, KC=128, fp16 mma, Sh consumed via ldmatrix.trans.
__global__ __launch_bounds__(256, 1) void k_tgemm2() {
    extern __shared__ char smc[];
    half* As = (half*)smc;                 // [2][128][HP]  (e rows, i cols)
    half* Bs = As + 2 * 128 * HP;          // [2][128][HP]  (i rows, j cols)
    const int stA = 128 * HP, stB = 128 * HP;
    int tid = threadIdx.x, lane = tid & 31, wid = tid >> 5;
    int wm = wid & 3, wn = wid >> 2;       // 4m x 2n
    int b = blockIdx.y;
    int j0 = blockIdx.x * 128;
    const half* Ab = g_UidTh + (size_t)b * E * L;
    const half* Sb = g_Sh + (size_t)b * L * L;
    uint32_t aB = smem_u32(As), bB = smem_u32(Bs);

    auto load = [&](int t) {
        int k0 = t * 128, s = t & 1;
#pragma unroll
        for (int p = 0; p < 8; p++) {
            int idx = tid + p * 256;
            int row = idx >> 4, q = (idx & 15) * 8;
            cpa16(aB + (s * stA + row * HP + q) * 2, Ab + (size_t)row * L + k0 + q);
        }
#pragma unroll
        for (int p = 0; p < 8; p++) {
            int idx = tid + p * 256;
            int row = idx >> 4, q = (idx & 15) * 8;
            cpa16(bB + (s * stB + row * HP + q) * 2, Sb + (size_t)(k0 + row) * L + j0 + q);
        }
        cpa_commit();
    };

    float acc[2][8][4];
#pragma unroll
    for (int mi = 0; mi < 2; mi++)
#pragma unroll
        for (int nt = 0; nt < 8; nt++)
#pragma unroll
            for (int q = 0; q < 4; q++) acc[mi][nt][q] = 0.f;

    const int iters = L / 128;
    load(0); load(1);
    for (int t = 0; t < iters; t++) {
        int s = t & 1;
        if (t + 1 < iters) cpa_wait1(); else cpa_wait0();
        __syncthreads();
#pragma unroll
        for (int kk = 0; kk < 8; kk++) {
            uint32_t a[2][4], bf[4][4];
#pragma unroll
            for (int mi = 0; mi < 2; mi++)
                ldsm4(aB + (s * stA + (wm * 32 + mi * 16 + (lane & 15)) * HP + kk * 16 + (lane >> 4) * 8) * 2, a[mi]);
#pragma unroll
            for (int n4 = 0; n4 < 4; n4++)
                ldsm4t(bB + (s * stB + (kk * 16 + (lane & 15)) * HP + wn * 64 + n4 * 16 + (lane >> 4) * 8) * 2, bf[n4]);
#pragma unroll
            for (int n4 = 0; n4 < 4; n4++)
#pragma unroll
                for (int mi = 0; mi < 2; mi++) {
                    mma16816(acc[mi][n4 * 2 + 0], a[mi], bf[n4][0], bf[n4][1]);
                    mma16816(acc[mi][n4 * 2 + 1], a[mi], bf[n4][2], bf[n4][3]);
                }
        }
        __syncthreads();
        if (t + 2 < iters) load(t + 2);
    }

#pragma unroll
    for (int mi = 0; mi < 2; mi++) {
        int e0r = wm * 32 + mi * 16 + (lane >> 2);
#pragma unroll
        for (int nt = 0; nt < 8; nt++) {
            int j = j0 + wn * 64 + nt * 8 + (lane & 3) * 2;
            float2 iv = *(const float2*)&g_invd[b * L + j];
            float s0 = iv.x * iv.x * 16384.0f, s1 = iv.y * iv.y * 16384.0f;
            *(half2*)&g_Th[((size_t)b * E + e0r) * L + j] =
                __floats2half2_rn(acc[mi][nt][0] * s0, acc[mi][nt][1] * s1);
            *(half2*)&g_Th[((size_t)b * E + e0r + 8) * L + j] =
                __floats2half2_rn(acc[mi][nt][2] * s0, acc[mi][nt][3] * s1);
        }
    }
}

// ---------------- kernel 6: [A_D2Q | A_Q2D] = Sh @ [Uqsh | Th]^T ------------
// CTA 128m x 256n, 512 threads, KC=128, fp16 mma, fused concat epilogue.
__global__ __launch_bounds__(512, 1) void k_final(const float* __restrict__ Uid,
                                                  float* __restrict__ out) {
    extern __shared__ char smc[];
    half* As = (half*)smc;                 // [2][128][HP]
    half* Bs = As + 2 * 128 * HP;          // [2][256][HP]
    const int stA = 128 * HP, stB = 256 * HP;
    int tid = threadIdx.x, lane = tid & 31, wid = tid >> 5;
    int wm = wid & 3, wn = wid >> 2;       // 4m x 4n
    int b = blockIdx.y;
    int i0 = blockIdx.x * 128;
    const half* Sb  = g_Sh   + (size_t)b * L * L + (size_t)i0 * L;
    const half* B1g = g_Uqsh + (size_t)b * E * L;
    const half* B2g = g_Th   + (size_t)b * E * L;
    uint32_t aB = smem_u32(As), bB = smem_u32(Bs);

    auto load = [&](int t) {
        int k0 = t * 128, s = t & 1;
#pragma unroll
        for (int p = 0; p < 4; p++) {
            int idx = tid + p * 512;
            int row = idx >> 4, q = (idx & 15) * 8;
            cpa16(aB + (s * stA + row * HP + q) * 2, Sb + (size_t)row * L + k0 + q);
        }
#pragma unroll
        for (int p = 0; p < 8; p++) {
            int idx = tid + p * 512;
            int row = idx >> 4, q = (idx & 15) * 8;
            const half* src = row < 128 ? B1g + (size_t)row * L + k0 + q
                                        : B2g + (size_t)(row - 128) * L + k0 + q;
            cpa16(bB + (s * stB + row * HP + q) * 2, src);
        }
        cpa_commit();
    };

    float acc[2][8][4];
#pragma unroll
    for (int mi = 0; mi < 2; mi++)
#pragma unroll
        for (int nt = 0; nt < 8; nt++)
#pragma unroll
            for (int q = 0; q < 4; q++) acc[mi][nt][q] = 0.f;

    const int iters = L / 128;
    load(0); load(1);
    for (int t = 0; t < iters; t++) {
        int s = t & 1;
        if (t + 1 < iters) cpa_wait1(); else cpa_wait0();
        __syncthreads();
#pragma unroll
        for (int kk = 0; kk < 8; kk++) {
            uint32_t a[2][4], bf[4][4];
#pragma unroll
            for (int mi = 0; mi < 2; mi++)
                ldsm4(aB + (s * stA + (wm * 32 + mi * 16 + (lane & 15)) * HP + kk * 16 + (lane >> 4) * 8) * 2, a[mi]);
#pragma unroll
            for (int n4 = 0; n4 < 4; n4++)
                ldsm4(bB + (s * stB + (wn * 64 + n4 * 16 + (lane & 15)) * HP + kk * 16 + (lane >> 4) * 8) * 2, bf[n4]);
#pragma unroll
            for (int n4 = 0; n4 < 4; n4++)
#pragma unroll
                for (int mi = 0; mi < 2; mi++) {
                    mma16816(acc[mi][n4 * 2 + 0], a[mi], bf[n4][0], bf[n4][2]);
                    mma16816(acc[mi][n4 * 2 + 1], a[mi], bf[n4][1], bf[n4][3]);
                }
        }
        __syncthreads();
        if (t + 2 < iters) load(t + 2);
    }

    // epilogue: out row i: [Uid | A_D2Q | Uid*A_D2Q | Uid*A_Q2D]
#pragma unroll
    for (int mi = 0; mi < 2; mi++) {
        int r0 = i0 + wm * 32 + mi * 16 + (lane >> 2);
#pragma unroll
        for (int nt = 0; nt < 8; nt++) {
            int n = wn * 64 + nt * 8 + (lane & 3) * 2;   // 0..255
#pragma unroll
            for (int h = 0; h < 2; h++) {
                int gi = r0 + h * 8;
                float v0 = acc[mi][nt][h * 2], v1 = acc[mi][nt][h * 2 + 1];
                float* orow = out + ((size_t)b * L + gi) * (4 * E);
                if (n < 128) {
                    v0 *= SC_QI; v1 *= SC_QI;
                    float2 u = *(const float2*)&Uid[((size_t)b * L + gi) * E + n];
                    *(float2*)&orow[128 + n] = make_float2(v0, v1);
                    *(float2*)&orow[256 + n] = make_float2(v0 * u.x, v1 * u.y);
                } else {
                    int m = n - 128;
                    v0 *= SC_TI; v1 *= SC_TI;
                    float2 u = *(const float2*)&Uid[((size_t)b * L + gi) * E + m];
                    *(float2*)&orow[384 + m] = make_float2(v0 * u.x, v1 * u.y);
                }
            }
        }
    }
    // Uid copy into slot 0
#pragma unroll
    for (int p = 0; p < 8; p++) {
        int idx = tid + p * 512;
        int row = idx >> 5, c = (idx & 31) * 4;
        int gi = i0 + row;
        *(float4*)&out[((size_t)b * L + gi) * (4 * E) + c] =
            *(const float4*)&Uid[((size_t)b * L + gi) * E + c];
    }
}

// ---------------- launch ----------------------------------------------------
extern "C" void kernel_launch(void* const* d_in, const int* in_sizes, int n_in,
                              void* d_out, int out_size) {
    const float* Uq   = (const float*)d_in[0];
    const float* Uid  = (const float*)d_in[1];
    const float* mask = (const float*)d_in[2];
    const float* Wc_w = (const float*)d_in[3];
    const float* Wc_b = (const float*)d_in[4];
    float* out = (float*)d_out;

    const int SMEM_SG = 2 * 128 * HP * 2 + 128 * 4;        // 70144
    const int SMEM_TG = 2 * 2 * 128 * HP * 2;              // 139264
    const int SMEM_FI = 2 * (128 + 256) * HP * 2;          // 208896
    cudaFuncSetAttribute(k_sgemm,  cudaFuncAttributeMaxDynamicSharedMemorySize, SMEM_SG);
    cudaFuncSetAttribute(k_tgemm2, cudaFuncAttributeMaxDynamicSharedMemorySize, SMEM_TG);
    cudaFuncSetAttribute(k_final,  cudaFuncAttributeMaxDynamicSharedMemorySize, SMEM_FI);

    k_dots<<<(B * L) / 8, dim3(32, 8)>>>(Uq, Uid, Wc_w);
    k_prep<<<(B * L * E) / 1024, 256>>>(Uq, Uid, Wc_w);
    k_sgemm<<<dim3(L / 128, L / 128, B), 256, SMEM_SG>>>(mask, Wc_b);
    k_inv<<<(B * L) / 256, 256>>>();
    k_trans<<<dim3(L / 32, E / 32, 2 * B), dim3(32, 8)>>>(Uid, Uq);
    k_tgemm2<<<dim3(L / 128, B), 256, SMEM_TG>>>();
    k_final<<<dim3(L / 128, B), 512, SMEM_FI>>>(Uid, out);
}

// round 7
// speedup vs baseline: 1.8762x; 1.0622x over previous
#include <cuda_runtime.h>
#include <cuda_fp16.h>
#include <cstdint>
#include <cstddef>

#define B 8
#define L 2048
#define E 128
#define HP 136                     // smem pitch in halves (272B, ldmatrix conflict-free)

// ---------------- scratch (device globals) ----------------------------------
__device__ half g_Sh[(size_t)B * L * L];      // fp16(exp(S*mask))            67 MB
__device__ half g_Th[(size_t)B * E * L];      // fp16(invd^2 * G2 * 2^14)   [e][j]
__device__ half g_Uqsh[(size_t)B * E * L];    // fp16(invd * Uq^T * 2^10)   [e][j]
__device__ half g_UidTh[(size_t)B * E * L];   // fp16(Uid^T)                [e][i]
__device__ half g_Uidwh[(size_t)B * L * E];   // fp16(Uid * wmul)           [i][e]
__device__ half g_Uqh[(size_t)B * L * E];     // fp16(Uq)                   [j][e]
__device__ float g_sid[B * L];
__device__ float g_sq[B * L];
__device__ float g_d[B * L];

#define SC_QI 0.0009765625f        // 2^-10
#define SC_TI 6.103515625e-05f     // 2^-14

// ---------------- helpers ----------------------------------------------------
__device__ __forceinline__ uint32_t smem_u32(const void* p) {
    uint32_t a;
    asm("{ .reg .u64 t; cvta.to.shared.u64 t, %1; cvt.u32.u64 %0, t; }"
        : "=r"(a) : "l"(p));
    return a;
}
__device__ __forceinline__ void ldsm4(uint32_t addr, uint32_t r[4]) {
    asm volatile("ldmatrix.sync.aligned.m8n8.x4.shared.b16 {%0,%1,%2,%3}, [%4];"
                 : "=r"(r[0]), "=r"(r[1]), "=r"(r[2]), "=r"(r[3]) : "r"(addr));
}
__device__ __forceinline__ void ldsm4t(uint32_t addr, uint32_t r[4]) {
    asm volatile("ldmatrix.sync.aligned.m8n8.x4.trans.shared.b16 {%0,%1,%2,%3}, [%4];"
                 : "=r"(r[0]), "=r"(r[1]), "=r"(r[2]), "=r"(r[3]) : "r"(addr));
}
__device__ __forceinline__ void mma16816(float c[4], const uint32_t a[4],
                                         uint32_t b0, uint32_t b1) {
    asm volatile(
        "mma.sync.aligned.m16n8k16.row.col.f32.f16.f16.f32 "
        "{%0,%1,%2,%3}, {%4,%5,%6,%7}, {%8,%9}, {%0,%1,%2,%3};"
        : "+f"(c[0]), "+f"(c[1]), "+f"(c[2]), "+f"(c[3])
        : "r"(a[0]), "r"(a[1]), "r"(a[2]), "r"(a[3]), "r"(b0), "r"(b1));
}
__device__ __forceinline__ void cpa16(uint32_t dst, const void* src) {
    asm volatile("cp.async.cg.shared.global [%0], [%1], 16;"
                 :: "r"(dst), "l"(src) : "memory");
}
__device__ __forceinline__ void cpa_commit() {
    asm volatile("cp.async.commit_group;" ::: "memory");
}
__device__ __forceinline__ void cpa_wait1() {
    asm volatile("cp.async.wait_group 1;" ::: "memory");
}
__device__ __forceinline__ void cpa_wait0() {
    asm volatile("cp.async.wait_group 0;" ::: "memory");
}

// ---------------- kernel 1: row dots s_id, s_q + zero g_d -------------------
__global__ void k_dots(const float* __restrict__ Uq,
                       const float* __restrict__ Uid,
                       const float* __restrict__ Wc_w) {
    int r = blockIdx.x * 8 + threadIdx.y;
    int lane = threadIdx.x;
    float sid = 0.f, sq = 0.f;
#pragma unroll
    for (int t = 0; t < 4; t++) {
        int e = lane + t * 32;
        sid += Uid[(size_t)r * E + e] * Wc_w[e];
        sq  += Uq [(size_t)r * E + e] * Wc_w[E + e];
    }
#pragma unroll
    for (int o = 16; o; o >>= 1) {
        sid += __shfl_xor_sync(0xffffffffu, sid, o);
        sq  += __shfl_xor_sync(0xffffffffu, sq,  o);
    }
    if (lane == 0) { g_sid[r] = sid; g_sq[r] = sq; g_d[r] = 0.f; }
}

// ---------------- kernel 1b: fp16 operands + UidT transpose -----------------
// per 32x32 (l, e) tile: writes Uidwh, Uqh (row-major) and UidTh (transposed).
__global__ void k_prep(const float* __restrict__ Uq,
                       const float* __restrict__ Uid,
                       const float* __restrict__ Wc_w) {
    __shared__ float tu[32][33];
    int l0 = blockIdx.x * 32, e0 = blockIdx.y * 32, b = blockIdx.z;
    int tx = threadIdx.x, ty = threadIdx.y;
    const float* ub = Uid + (size_t)b * L * E;
    const float* qb = Uq  + (size_t)b * L * E;
    float w = Wc_w[2 * E + e0 + tx];
#pragma unroll
    for (int r = 0; r < 4; r++) {
        int row = l0 + ty + r * 8;
        float u = ub[(size_t)row * E + e0 + tx];
        float q = qb[(size_t)row * E + e0 + tx];
        g_Uidwh[((size_t)b * L + row) * E + e0 + tx] = __float2half_rn(u * w);
        g_Uqh  [((size_t)b * L + row) * E + e0 + tx] = __float2half_rn(q);
        tu[ty + r * 8][tx] = u;
    }
    __syncthreads();
#pragma unroll
    for (int r = 0; r < 4; r++) {
        int e = e0 + ty + r * 8;
        g_UidTh[((size_t)b * E + e) * L + l0 + tx] =
            __float2half_rn(tu[tx][ty + r * 8]);
    }
}

// ---------------- kernel 2: Sh = fp16(exp(S*mask)) + column sums ------------
// per-(b,i0,j0) CTA; fp16 mma K=128 single-shot; smem-staged coalesced store.
__global__ __launch_bounds__(256, 2) void k_sgemm(const float* __restrict__ mask,
                                                  const float* __restrict__ Wc_b) {
    extern __shared__ char smc[];
    half* Ah = (half*)smc;                       // [128][HP]
    half* Bh = Ah + 128 * HP;                    // [128][HP]
    float* red = (float*)(Bh + 128 * HP);        // [128]
    half* stage = Ah;                            // reused post-mma (same size)
    int b  = blockIdx.z;
    int i0 = blockIdx.y * 128;
    int j0 = blockIdx.x * 128;
    int tid = threadIdx.x, lane = tid & 31, wid = tid >> 5;
    int wm = wid & 3, wn = wid >> 2;             // 4m x 2n warps, tile 32x64
    const half* A  = g_Uidwh + (size_t)b * L * E;
    const half* Bq = g_Uqh   + (size_t)b * L * E;
    uint32_t aB = smem_u32(Ah), bB = smem_u32(Bh);

#pragma unroll
    for (int p = 0; p < 8; p++) {
        int idx = tid + p * 256;
        int row = idx >> 4, q = (idx & 15) * 8;
        cpa16(aB + (row * HP + q) * 2, A + (size_t)(i0 + row) * E + q);
    }
#pragma unroll
    for (int p = 0; p < 8; p++) {
        int idx = tid + p * 256;
        int row = idx >> 4, q = (idx & 15) * 8;
        cpa16(bB + (row * HP + q) * 2, Bq + (size_t)(j0 + row) * E + q);
    }
    cpa_commit();
    if (tid < 128) red[tid] = 0.f;
    cpa_wait0();
    __syncthreads();

    float acc[2][8][4];
#pragma unroll
    for (int mi = 0; mi < 2; mi++)
#pragma unroll
        for (int nt = 0; nt < 8; nt++)
#pragma unroll
            for (int q = 0; q < 4; q++) acc[mi][nt][q] = 0.f;

#pragma unroll
    for (int kk = 0; kk < 8; kk++) {
        uint32_t a[2][4], bf[4][4];
#pragma unroll
        for (int mi = 0; mi < 2; mi++)
            ldsm4(aB + ((wm * 32 + mi * 16 + (lane & 15)) * HP + kk * 16 + (lane >> 4) * 8) * 2, a[mi]);
#pragma unroll
        for (int n4 = 0; n4 < 4; n4++)
            ldsm4(bB + ((wn * 64 + n4 * 16 + (lane & 15)) * HP + kk * 16 + (lane >> 4) * 8) * 2, bf[n4]);
#pragma unroll
        for (int n4 = 0; n4 < 4; n4++)
#pragma unroll
            for (int mi = 0; mi < 2; mi++) {
                mma16816(acc[mi][n4 * 2 + 0], a[mi], bf[n4][0], bf[n4][2]);
                mma16816(acc[mi][n4 * 2 + 1], a[mi], bf[n4][1], bf[n4][3]);
            }
    }
    __syncthreads();   // all ldsm done before stage overwrites Ah

    float bias = *Wc_b;
    float cs0[8], cs1[8];
#pragma unroll
    for (int nt = 0; nt < 8; nt++) { cs0[nt] = 0.f; cs1[nt] = 0.f; }
#pragma unroll
    for (int mi = 0; mi < 2; mi++) {
        int r0l = wm * 32 + mi * 16 + (lane >> 2);
        int r0 = i0 + r0l;
        float sidv0 = g_sid[b * L + r0];
        float sidv1 = g_sid[b * L + r0 + 8];
#pragma unroll
        for (int nt = 0; nt < 8; nt++) {
            int nl = wn * 64 + nt * 8 + (lane & 3) * 2;
            int n = j0 + nl;
            float2 sq2 = *(const float2*)&g_sq[b * L + n];
            float2 mk0 = *(const float2*)&mask[(size_t)r0 * L + n];
            float2 mk1 = *(const float2*)&mask[(size_t)(r0 + 8) * L + n];
            float e0 = __expf((acc[mi][nt][0] + sidv0 + sq2.x + bias) * mk0.x);
            float e1 = __expf((acc[mi][nt][1] + sidv0 + sq2.y + bias) * mk0.y);
            float e2 = __expf((acc[mi][nt][2] + sidv1 + sq2.x + bias) * mk1.x);
            float e3 = __expf((acc[mi][nt][3] + sidv1 + sq2.y + bias) * mk1.y);
            half2 h01 = __floats2half2_rn(e0, e1);
            half2 h23 = __floats2half2_rn(e2, e3);
            *(half2*)&stage[r0l * HP + nl]       = h01;
            *(half2*)&stage[(r0l + 8) * HP + nl] = h23;
            cs0[nt] += __low2float(h01) + __low2float(h23);
            cs1[nt] += __high2float(h01) + __high2float(h23);
        }
    }
#pragma unroll
    for (int o = 16; o >= 4; o >>= 1)
#pragma unroll
        for (int nt = 0; nt < 8; nt++) {
            cs0[nt] += __shfl_xor_sync(0xffffffffu, cs0[nt], o);
            cs1[nt] += __shfl_xor_sync(0xffffffffu, cs1[nt], o);
        }
    if ((lane >> 2) == 0) {
#pragma unroll
        for (int nt = 0; nt < 8; nt++) {
            int nl = wn * 64 + nt * 8 + (lane & 3) * 2;
            atomicAdd(&red[nl], cs0[nt]);
            atomicAdd(&red[nl + 1], cs1[nt]);
        }
    }
    __syncthreads();   // stage + red complete

    half* Sout = g_Sh + (size_t)b * L * L;
#pragma unroll
    for (int p = 0; p < 8; p++) {
        int idx = tid + p * 256;
        int row = idx >> 4, q = (idx & 15) * 8;
        *(float4*)&Sout[(size_t)(i0 + row) * L + j0 + q] =
            *(const float4*)&stage[row * HP + q];
    }
    if (tid < 128) atomicAdd(&g_d[(size_t)b * L + j0 + tid], red[tid]);
}

// ---------------- kernel 4: Uqsh[e][j] = fp16(Uq[j,e] * 2^10 / d[j]) --------
__global__ void k_trans(const float* __restrict__ Uq) {
    __shared__ float t[32][33];
    int l0 = blockIdx.x * 32, e0 = blockIdx.y * 32, b = blockIdx.z;
    const float* src = Uq + (size_t)b * L * E;
    int tx = threadIdx.x, ty = threadIdx.y;
#pragma unroll
    for (int r = 0; r < 4; r++)
        t[ty + r * 8][tx] = src[(size_t)(l0 + ty + r * 8) * E + e0 + tx];
    __syncthreads();
    float inv = __fdividef(1024.0f, g_d[b * L + l0 + tx]);
    half* dst = g_Uqsh + (size_t)b * E * L;
#pragma unroll
    for (int r = 0; r < 4; r++)
        dst[(size_t)(e0 + ty + r * 8) * L + l0 + tx] =
            __float2half_rn(t[tx][ty + r * 8] * inv);
}

// ---------------- kernel 5: Th = fp16((UidTh @ Sh) * 2^14 / d^2) ------------
// C[e][j] over K=i, KC=128, fp16 mma, Sh consumed via ldmatrix.trans.
__global__ __launch_bounds__(256, 1) void k_tgemm2() {
    extern __shared__ char smc[];
    half* As = (half*)smc;                 // [2][128][HP]  (e rows, i cols)
    half* Bs = As + 2 * 128 * HP;          // [2][128][HP]  (i rows, j cols)
    const int stA = 128 * HP, stB = 128 * HP;
    int tid = threadIdx.x, lane = tid & 31, wid = tid >> 5;
    int wm = wid & 3, wn = wid >> 2;       // 4m x 2n
    int b = blockIdx.y;
    int j0 = blockIdx.x * 128;
    const half* Ab = g_UidTh + (size_t)b * E * L;
    const half* Sb = g_Sh + (size_t)b * L * L;
    uint32_t aB = smem_u32(As), bB = smem_u32(Bs);

    auto load = [&](int t) {
        int k0 = t * 128, s = t & 1;
#pragma unroll
        for (int p = 0; p < 8; p++) {
            int idx = tid + p * 256;
            int row = idx >> 4, q = (idx & 15) * 8;
            cpa16(aB + (s * stA + row * HP + q) * 2, Ab + (size_t)row * L + k0 + q);
        }
#pragma unroll
        for (int p = 0; p < 8; p++) {
            int idx = tid + p * 256;
            int row = idx >> 4, q = (idx & 15) * 8;
            cpa16(bB + (s * stB + row * HP + q) * 2, Sb + (size_t)(k0 + row) * L + j0 + q);
        }
        cpa_commit();
    };

    float acc[2][8][4];
#pragma unroll
    for (int mi = 0; mi < 2; mi++)
#pragma unroll
        for (int nt = 0; nt < 8; nt++)
#pragma unroll
            for (int q = 0; q < 4; q++) acc[mi][nt][q] = 0.f;

    const int iters = L / 128;
    load(0); load(1);
    for (int t = 0; t < iters; t++) {
        int s = t & 1;
        if (t + 1 < iters) cpa_wait1(); else cpa_wait0();
        __syncthreads();
#pragma unroll
        for (int kk = 0; kk < 8; kk++) {
            uint32_t a[2][4], bf[4][4];
#pragma unroll
            for (int mi = 0; mi < 2; mi++)
                ldsm4(aB + (s * stA + (wm * 32 + mi * 16 + (lane & 15)) * HP + kk * 16 + (lane >> 4) * 8) * 2, a[mi]);
#pragma unroll
            for (int n4 = 0; n4 < 4; n4++)
                ldsm4t(bB + (s * stB + (kk * 16 + (lane & 15)) * HP + wn * 64 + n4 * 16 + (lane >> 4) * 8) * 2, bf[n4]);
#pragma unroll
            for (int n4 = 0; n4 < 4; n4++)
#pragma unroll
                for (int mi = 0; mi < 2; mi++) {
                    mma16816(acc[mi][n4 * 2 + 0], a[mi], bf[n4][0], bf[n4][1]);
                    mma16816(acc[mi][n4 * 2 + 1], a[mi], bf[n4][2], bf[n4][3]);
                }
        }
        __syncthreads();
        if (t + 2 < iters) load(t + 2);
    }

#pragma unroll
    for (int mi = 0; mi < 2; mi++) {
        int e0r = wm * 32 + mi * 16 + (lane >> 2);
#pragma unroll
        for (int nt = 0; nt < 8; nt++) {
            int j = j0 + wn * 64 + nt * 8 + (lane & 3) * 2;
            float2 dv = *(const float2*)&g_d[b * L + j];
            float s0 = __fdividef(16384.0f, dv.x * dv.x);
            float s1 = __fdividef(16384.0f, dv.y * dv.y);
            *(half2*)&g_Th[((size_t)b * E + e0r) * L + j] =
                __floats2half2_rn(acc[mi][nt][0] * s0, acc[mi][nt][1] * s1);
            *(half2*)&g_Th[((size_t)b * E + e0r + 8) * L + j] =
                __floats2half2_rn(acc[mi][nt][2] * s0, acc[mi][nt][3] * s1);
        }
    }
}

// ---------------- kernel 6: [A_D2Q | A_Q2D] = Sh @ [Uqsh | Th]^T ------------
// CTA 128m x 256n, 512 threads, KC=128, fp16 mma, fused concat epilogue.
__global__ __launch_bounds__(512, 1) void k_final(const float* __restrict__ Uid,
                                                  float* __restrict__ out) {
    extern __shared__ char smc[];
    half* As = (half*)smc;                 // [2][128][HP]
    half* Bs = As + 2 * 128 * HP;          // [2][256][HP]
    const int stA = 128 * HP, stB = 256 * HP;
    int tid = threadIdx.x, lane = tid & 31, wid = tid >> 5;
    int wm = wid & 3, wn = wid >> 2;       // 4m x 4n
    int b = blockIdx.y;
    int i0 = blockIdx.x * 128;
    const half* Sb  = g_Sh   + (size_t)b * L * L + (size_t)i0 * L;
    const half* B1g = g_Uqsh + (size_t)b * E * L;
    const half* B2g = g_Th   + (size_t)b * E * L;
    uint32_t aB = smem_u32(As), bB = smem_u32(Bs);

    auto load = [&](int t) {
        int k0 = t * 128, s = t & 1;
#pragma unroll
        for (int p = 0; p < 4; p++) {
            int idx = tid + p * 512;
            int row = idx >> 4, q = (idx & 15) * 8;
            cpa16(aB + (s * stA + row * HP + q) * 2, Sb + (size_t)row * L + k0 + q);
        }
#pragma unroll
        for (int p = 0; p < 8; p++) {
            int idx = tid + p * 512;
            int row = idx >> 4, q = (idx & 15) * 8;
            const half* src = row < 128 ? B1g + (size_t)row * L + k0 + q
                                        : B2g + (size_t)(row - 128) * L + k0 + q;
            cpa16(bB + (s * stB + row * HP + q) * 2, src);
        }
        cpa_commit();
    };

    float acc[2][8][4];
#pragma unroll
    for (int mi = 0; mi < 2; mi++)
#pragma unroll
        for (int nt = 0; nt < 8; nt++)
#pragma unroll
            for (int q = 0; q < 4; q++) acc[mi][nt][q] = 0.f;

    const int iters = L / 128;
    load(0); load(1);
    for (int t = 0; t < iters; t++) {
        int s = t & 1;
        if (t + 1 < iters) cpa_wait1(); else cpa_wait0();
        __syncthreads();
#pragma unroll
        for (int kk = 0; kk < 8; kk++) {
            uint32_t a[2][4], bf[4][4];
#pragma unroll
            for (int mi = 0; mi < 2; mi++)
                ldsm4(aB + (s * stA + (wm * 32 + mi * 16 + (lane & 15)) * HP + kk * 16 + (lane >> 4) * 8) * 2, a[mi]);
#pragma unroll
            for (int n4 = 0; n4 < 4; n4++)
                ldsm4(bB + (s * stB + (wn * 64 + n4 * 16 + (lane & 15)) * HP + kk * 16 + (lane >> 4) * 8) * 2, bf[n4]);
#pragma unroll
            for (int n4 = 0; n4 < 4; n4++)
#pragma unroll
                for (int mi = 0; mi < 2; mi++) {
                    mma16816(acc[mi][n4 * 2 + 0], a[mi], bf[n4][0], bf[n4][2]);
                    mma16816(acc[mi][n4 * 2 + 1], a[mi], bf[n4][1], bf[n4][3]);
                }
        }
        __syncthreads();
        if (t + 2 < iters) load(t + 2);
    }

    // epilogue: out row i: [Uid | A_D2Q | Uid*A_D2Q | Uid*A_Q2D]
#pragma unroll
    for (int mi = 0; mi < 2; mi++) {
        int r0 = i0 + wm * 32 + mi * 16 + (lane >> 2);
#pragma unroll
        for (int nt = 0; nt < 8; nt++) {
            int n = wn * 64 + nt * 8 + (lane & 3) * 2;   // 0..255
#pragma unroll
            for (int h = 0; h < 2; h++) {
                int gi = r0 + h * 8;
                float v0 = acc[mi][nt][h * 2], v1 = acc[mi][nt][h * 2 + 1];
                float* orow = out + ((size_t)b * L + gi) * (4 * E);
                if (n < 128) {
                    v0 *= SC_QI; v1 *= SC_QI;
                    float2 u = *(const float2*)&Uid[((size_t)b * L + gi) * E + n];
                    *(float2*)&orow[128 + n] = make_float2(v0, v1);
                    *(float2*)&orow[256 + n] = make_float2(v0 * u.x, v1 * u.y);
                } else {
                    int m = n - 128;
                    v0 *= SC_TI; v1 *= SC_TI;
                    float2 u = *(const float2*)&Uid[((size_t)b * L + gi) * E + m];
                    *(float2*)&orow[384 + m] = make_float2(v0 * u.x, v1 * u.y);
                }
            }
        }
    }
    // Uid copy into slot 0
#pragma unroll
    for (int p = 0; p < 8; p++) {
        int idx = tid + p * 512;
        int row = idx >> 5, c = (idx & 31) * 4;
        int gi = i0 + row;
        *(float4*)&out[((size_t)b * L + gi) * (4 * E) + c] =
            *(const float4*)&Uid[((size_t)b * L + gi) * E + c];
    }
}

// ---------------- launch ----------------------------------------------------
extern "C" void kernel_launch(void* const* d_in, const int* in_sizes, int n_in,
                              void* d_out, int out_size) {
    const float* Uq   = (const float*)d_in[0];
    const float* Uid  = (const float*)d_in[1];
    const float* mask = (const float*)d_in[2];
    const float* Wc_w = (const float*)d_in[3];
    const float* Wc_b = (const float*)d_in[4];
    float* out = (float*)d_out;

    const int SMEM_SG = 2 * 128 * HP * 2 + 128 * 4;        // 70144
    const int SMEM_TG = 2 * 2 * 128 * HP * 2;              // 139264
    const int SMEM_FI = 2 * (128 + 256) * HP * 2;          // 208896
    cudaFuncSetAttribute(k_sgemm,  cudaFuncAttributeMaxDynamicSharedMemorySize, SMEM_SG);
    cudaFuncSetAttribute(k_tgemm2, cudaFuncAttributeMaxDynamicSharedMemorySize, SMEM_TG);
    cudaFuncSetAttribute(k_final,  cudaFuncAttributeMaxDynamicSharedMemorySize, SMEM_FI);

    k_dots<<<(B * L) / 8, dim3(32, 8)>>>(Uq, Uid, Wc_w);
    k_prep<<<dim3(L / 32, E / 32, B), dim3(32, 8)>>>(Uq, Uid, Wc_w);
    k_sgemm<<<dim3(L / 128, L / 128, B), 256, SMEM_SG>>>(mask, Wc_b);
    k_trans<<<dim3(L / 32, E / 32, B), dim3(32, 8)>>>(Uq);
    k_tgemm2<<<dim3(L / 128, B), 256, SMEM_TG>>>();
    k_final<<<dim3(L / 128, B), 512, SMEM_FI>>>(Uid, out);
}